// round 10
// baseline (speedup 1.0000x reference)
#include <cuda_runtime.h>
#include <math.h>

// ChargeEquilibrationBlock: B=1024 molecules x n=128 atoms.
// Packed-triangle blocked Cholesky (NB=32), lookahead, fused forward solve,
// register-resident panel, conflict-free vector smem paths (R9 structure).
// R10: branchless fast erf (A&S 7.1.26, |err|<=1.5e-7) + sqrt(2) folded
// into the gamma rsqrt -> shorter build chains. 6 CTAs/SM.

#define NMOL 1024
#define NA   128
#define NB   32
#define NE   10
#define FULL 0xffffffffu
#define TRI_WORDS 8448   // rowp(128)

typedef unsigned long long ull;

// packed row offset: rows padded to multiple of 4 words (16B aligned)
__device__ __forceinline__ int rowp(int i) {
    const int q = i >> 2, r = i & 3;
    return ((q * (q - 1)) << 3) + ((r * q) << 2) + (i << 2);
}

__device__ __forceinline__ ull fma2(ull a, ull b, ull c) {
    ull d;
    asm("fma.rn.f32x2 %0, %1, %2, %3;" : "=l"(d) : "l"(a), "l"(b), "l"(c));
    return d;
}
__device__ __forceinline__ float hsum2(ull a) {
    return __uint_as_float((unsigned)a) + __uint_as_float((unsigned)(a >> 32));
}

// Branchless erf for x >= 0: Abramowitz-Stegun 7.1.26, |abs err| <= 1.5e-7.
// RCP + EX2 (independent MUFUs) + 5 FMA.
__device__ __forceinline__ float erf_fast(float x) {
    float t = __fdividef(1.0f, fmaf(0.3275911f, x, 1.0f));
    float e = __expf(-x * x);
    float p = fmaf(1.061405429f, t, -1.453152027f);
    p = fmaf(p, t, 1.421413741f);
    p = fmaf(p, t, -0.284496736f);
    p = fmaf(p, t, 0.254829592f);
    return fmaf(-p * t, e, 1.0f);
}

// build entries (i, j) for j in [jlo, jhi) with j < i; 4 erf chains in
// flight, STS.128 fast path when the whole quad is valid.
__device__ __forceinline__ void build_range(float* A, const float4* pq,
                                            int i, int jlo, int jhi) {
    const float4 pi = pq[i];
    float* Ri = A + rowp(i);
    for (int g = (jlo & ~3); g < jhi; g += 4) {
        float v[4];
        #pragma unroll
        for (int k = 0; k < 4; k++) {
            int j = min(g + k, NA - 1);             // clamp: no OOB pq read
            float4 p = pq[j];                       // broadcast (lockstep)
            float dx = pi.x - p.x, dy = pi.y - p.y, dz = pi.z - p.z;
            float sq = dx * dx + dy * dy + dz * dz;
            float rd = rsqrtf(sq);                  // 1/d
            float g2 = rsqrtf(2.0f * (pi.w + p.w)); // 1/(sqrt2*gamma)
            v[k] = erf_fast(sq * rd * g2) * rd;     // erf(d/(sqrt2 gamma))/d
        }
        if (g >= jlo && g + 4 <= jhi && g + 3 < i) {
            *(float4*)&Ri[g] = make_float4(v[0], v[1], v[2], v[3]);
        } else {
            #pragma unroll
            for (int k = 0; k < 4; k++) {
                int j = g + k;
                if (j >= jlo && j < jhi && j < i) Ri[j] = v[k];
            }
        }
    }
}

// trailing units: row ti, j-groups [g0, g1) of block at column base s.
__device__ __forceinline__ void trail_units(float* A, int ti, int s,
                                            int g0, int g1) {
    float* Ti = A + rowp(ti);
    ull la[16];
    const ulonglong2* Lp = (const ulonglong2*)(Ti + s);
    #pragma unroll
    for (int q = 0; q < 8; q++) { ulonglong2 t = Lp[q]; la[2*q] = t.x; la[2*q+1] = t.y; }
    int j    = s + NB + 4 * g0;
    int joff = rowp(j);
    for (int jg = g0; jg < g1; jg++, j += 4) {
        const int len = j + 4;
        const ulonglong2* R0 = (const ulonglong2*)(A + joff           + s);
        const ulonglong2* R1 = (const ulonglong2*)(A + joff +   len   + s);
        const ulonglong2* R2 = (const ulonglong2*)(A + joff + 2*len   + s);
        const ulonglong2* R3 = (const ulonglong2*)(A + joff + 3*len   + s);
        ull a0 = 0ull, a1 = 0ull, a2 = 0ull, a3 = 0ull;
        #pragma unroll
        for (int q = 0; q < 8; q++) {               // broadcast LDS.128, lockstep j
            ulonglong2 c0 = R0[q], c1 = R1[q], c2 = R2[q], c3 = R3[q];
            a0 = fma2(la[2*q], c0.x, a0); a0 = fma2(la[2*q+1], c0.y, a0);
            a1 = fma2(la[2*q], c1.x, a1); a1 = fma2(la[2*q+1], c1.y, a1);
            a2 = fma2(la[2*q], c2.x, a2); a2 = fma2(la[2*q+1], c2.y, a2);
            a3 = fma2(la[2*q], c3.x, a3); a3 = fma2(la[2*q+1], c3.y, a3);
        }
        if (j <= ti) {                              // partial group -> padding
            float4 av = *(float4*)&Ti[j];
            av.x -= hsum2(a0); av.y -= hsum2(a1);
            av.z -= hsum2(a2); av.w -= hsum2(a3);
            *(float4*)&Ti[j] = av;
        }
        joff += 4 * len;
    }
}

// REGISTER-RESIDENT panel factorization + fused diag forward solve.
__device__ __noinline__ void panel_and_y(float* A, float* rinvS,
                                         float* xs1, float* xs2,
                                         int kb, int lane,
                                         float& v1, float& v2) {
    float* Arow = A + rowp(kb + lane);
    const int qmax = lane >> 2;                     // valid quads 0..qmax
    float r[NB];
    #pragma unroll
    for (int q = 0; q < 8; q++)
        if (q <= qmax) {
            float4 t = *(const float4*)&Arow[kb + 4 * q];
            r[4*q] = t.x; r[4*q+1] = t.y; r[4*q+2] = t.z; r[4*q+3] = t.w;
        }
    float rvown = 0.0f;
    #pragma unroll
    for (int m = 0; m < NB; m++) {
        const float dg = __shfl_sync(FULL, r[m], m);   // updated diag of row m
        const float rv = rsqrtf(dg);
        float lv;
        if (lane == m) { lv = dg * rv; rinvS[kb + m] = rv; rvown = rv; }
        else            lv = r[m] * rv;
        if (lane >= m) r[m] = lv;                   // L value (diag or below)
        lv = (lane > m) ? lv : 0.0f;                // update uses strict-below
        #pragma unroll
        for (int j = m + 1; j < NB; j++) {
            float ljm = __shfl_sync(FULL, lv, j);   // sources j > m: valid
            if (j <= lane) r[j] -= lv * ljm;
        }
    }
    // fused forward diag solve: L_bb y = b (L row in registers)
    #pragma unroll
    for (int m = 0; m < NB; m++) {
        float x1 = __shfl_sync(FULL, v1 * rvown, m);
        float x2 = __shfl_sync(FULL, v2 * rvown, m);
        if (lane > m) { v1 -= r[m] * x1; v2 -= r[m] * x2; }
    }
    v1 *= rvown; v2 *= rvown;                       // y for this row
    xs1[kb + lane] = v1; xs2[kb + lane] = v2;
    #pragma unroll
    for (int q = 0; q < 8; q++)                     // store L rows back
        if (q <= qmax)
            *(float4*)&Arow[kb + 4 * q] =
                make_float4(r[4*q], r[4*q+1], r[4*q+2], r[4*q+3]);
}

__global__ __launch_bounds__(NA, 6)
void ceq_kernel(const float* __restrict__ eneg,
                const float* __restrict__ pos,
                const float* __restrict__ attrs,
                const float* __restrict__ hard,
                const float* __restrict__ Qtot,
                const int*   __restrict__ Zs,
                float* __restrict__ out)
{
    extern __shared__ float s[];
    float*  A     = s;                    // packed lower triangle
    float*  rinvS = A + TRI_WORDS;        // 128: 1/L_ii
    float*  xs1   = rinvS + NA;           // solve broadcast, RHS 1
    float*  xs2   = xs1 + NA;             // solve broadcast, RHS 2
    float4* pq    = (float4*)(xs2 + NA);  // 128: (x, y, z, sigma)
    __shared__ float r1s[4], r2s[4];

    const int mol  = blockIdx.x;
    const int tid  = threadIdx.x;
    const int lane = tid & 31;
    const int wid  = tid >> 5;
    const int gid  = mol * NA + tid;
    float* Arow = A + rowp(tid);

    // ---- per-atom setup ----
    const float x = pos[gid * 3 + 0];
    const float y = pos[gid * 3 + 1];
    const float z = pos[gid * 3 + 2];
    const int Z = Zs[gid];
    const float r  = 0.3f + 0.02f * (float)Z;       // COV_RADII[Z]
    const float sg = r * r;
    pq[tid] = make_float4(x, y, z, sg);

    const float* arow = attrs + gid * NE;           // first-max argmax
    int am = 0; float mv = arow[0];
    #pragma unroll
    for (int e = 1; e < NE; e++) { float v = arow[e]; if (v > mv) { mv = v; am = e; } }

    const float diag = hard[am] + 1.0f / (1.7724538509055159f * r);  // sqrt(pi)
    float v1 = -eneg[gid];                          // RHS 1: -chi
    float v2 = 1.0f;                                // RHS 2: ones
    __syncthreads();                                // pq visible

    Arow[tid] = diag;                               // own diagonal

    // ---- build with panel-0 overlap ----
    if (wid == 0) {
        build_range(A, pq, lane, 0, 31);            // rows 0..31 (panel block)
        __syncwarp();
        panel_and_y(A, rinvS, xs1, xs2, 0, lane, v1, v2);
    } else if (wid == 1) {
        build_range(A, pq, 32 + lane, 0, 63);
        build_range(A, pq, 96 + lane, 0, 32);
    } else if (wid == 2) {
        build_range(A, pq, 64 + lane, 0, 95);
    } else {
        build_range(A, pq, 96 + lane, 32, 127);
    }
    __syncthreads();                                // BAR_A(0): build + panel0 + y0

    // ---- lookahead factorization ----
    for (int b = 0; b < 3; b++) {
        const int sb = 32 * b;

        // TRSM_b: rows below panel -> Lreg, float4 loads, fused fwd RHS
        if (tid >= sb + NB) {
            float Lreg[NB];
            int poff = rowp(sb);
            float4 aq;
            #pragma unroll
            for (int m = 0; m < NB; m++) {
                if ((m & 3) == 0)                   // quad-wise own-row load
                    aq = *(const float4*)&Arow[sb + m];
                const float am4 = ((m & 3) == 0) ? aq.x :
                                  ((m & 3) == 1) ? aq.y :
                                  ((m & 3) == 2) ? aq.z : aq.w;
                const float* Pm = A + poff + sb;    // panel row m (broadcast)
                float ve = 0.0f, vo = 0.0f;
                #pragma unroll
                for (int q = 0; q < NB / 4; q++) {
                    if (4 * q + 4 <= m) {           // full quads (compile-time)
                        float4 c = *(const float4*)(Pm + 4 * q);
                        ve += Lreg[4*q    ] * c.x + Lreg[4*q + 2] * c.z;
                        vo += Lreg[4*q + 1] * c.y + Lreg[4*q + 3] * c.w;
                    }
                }
                #pragma unroll
                for (int t = m & ~3; t < m; t++)    // remainder scalars
                    ve += Lreg[t] * Pm[t];
                Lreg[m] = (am4 - ve - vo) * rinvS[sb + m];
                poff += sb + (m & ~3) + 4;
            }
            #pragma unroll
            for (int m = 0; m < NB; m += 4)
                *(float4*)&Arow[sb + m] =
                    make_float4(Lreg[m], Lreg[m+1], Lreg[m+2], Lreg[m+3]);
            #pragma unroll
            for (int q = 0; q < NB; q += 4) {       // fused forward RHS update
                float4 a1 = *(const float4*)&xs1[sb + q];
                float4 a2 = *(const float4*)&xs2[sb + q];
                v1 -= Lreg[q]*a1.x + Lreg[q+1]*a1.y + Lreg[q+2]*a1.z + Lreg[q+3]*a1.w;
                v2 -= Lreg[q]*a2.x + Lreg[q+1]*a2.y + Lreg[q+2]*a2.z + Lreg[q+3]*a2.w;
            }
        }
        __syncthreads();                            // BAR_B(b): L columns visible

        // overlap slot: owner warp -> urgent own-rows + next panel;
        // other warps -> balanced lazy trailing of block b.
        if (b == 0) {
            if (wid == 1) {
                trail_units(A, tid, 0, 0, 8);       // own rows 32..63, cols 32..63
                __syncwarp();
                panel_and_y(A, rinvS, xs1, xs2, 32, lane, v1, v2);
            }
            else if (wid == 2) trail_units(A, 64 + lane, 0,  0, 16);
            else if (wid == 3) trail_units(A, 96 + lane, 0,  0, 12);
            else               trail_units(A, 96 + lane, 0, 12, 24);
        } else if (b == 1) {
            if (wid == 2) {
                trail_units(A, tid, 32, 0, 8);      // own rows 64..95, cols 64..95
                __syncwarp();
                panel_and_y(A, rinvS, xs1, xs2, 64, lane, v1, v2);
            }
            else if (wid == 3) trail_units(A, 96 + lane, 32,  0,  6);
            else if (wid == 1) trail_units(A, 96 + lane, 32,  6, 11);
            else               trail_units(A, 96 + lane, 32, 11, 16);
        } else {  // b == 2: 8 trailing units split across ALL warps, then panel 3
            trail_units(A, 96 + lane, 64, wid * 2, wid * 2 + 2);
            __syncthreads();
            if (wid == 3)
                panel_and_y(A, rinvS, xs1, xs2, 96, lane, v1, v2);
        }
        __syncthreads();                            // BAR_A(b+1)
    }
    // factorization + forward solve complete: v = y

    // ---- backward solve L^T x = y (2 RHS), blocked ----
    for (int b = 3; b >= 0; b--) {
        const int kb = b * NB;
        if (wid == b) {
            float lcol[NB];
            int coff = rowp(kb);
            #pragma unroll
            for (int m = 0; m < NB; m++) {
                lcol[m] = A[coff + tid];            // consecutive lanes: no conflict
                coff += kb + (m & ~3) + 4;
            }
            const float rv = rinvS[tid];
            #pragma unroll
            for (int m = NB - 1; m >= 0; m--) {
                float x1 = __shfl_sync(FULL, v1 * rv, m);
                float x2 = __shfl_sync(FULL, v2 * rv, m);
                if (lane < m) { v1 -= lcol[m] * x1; v2 -= lcol[m] * x2; }
            }
            v1 *= rv; v2 *= rv;
            xs1[tid] = v1; xs2[tid] = v2;
        }
        __syncthreads();
        if (tid < kb) {
            int coff = rowp(kb);
            #pragma unroll
            for (int m = 0; m < NB; m++) {
                float l = A[coff + tid];
                v1 -= l * xs1[kb + m];
                v2 -= l * xs2[kb + m];
                coff += kb + (m & ~3) + 4;
            }
        }
    }

    // v1 = A^{-1}(-chi), v2 = A^{-1} 1
    float s1 = v1, s2 = v2;
    #pragma unroll
    for (int o = 16; o > 0; o >>= 1) {
        s1 += __shfl_xor_sync(FULL, s1, o);
        s2 += __shfl_xor_sync(FULL, s2, o);
    }
    if (lane == 0) { r1s[wid] = s1; r2s[wid] = s2; }
    __syncthreads();
    s1 = r1s[0] + r1s[1] + r1s[2] + r1s[3];
    s2 = r2s[0] + r2s[1] + r2s[2] + r2s[3];

    const float lam = (s1 - Qtot[mol]) / (s2 - 1.0f);
    out[gid] = v1 - lam * v2;
}

extern "C" void kernel_launch(void* const* d_in, const int* in_sizes, int n_in,
                              void* d_out, int out_size)
{
    const float* eneg  = (const float*)d_in[0];
    const float* pos   = (const float*)d_in[1];
    const float* attrs = (const float*)d_in[2];
    const float* hard  = (const float*)d_in[3];
    const float* Qtot  = (const float*)d_in[4];
    const int*   Zs    = (const int*)d_in[6];
    float* out = (float*)d_out;

    const int smem = (TRI_WORDS + 3 * NA + NA * 4) * (int)sizeof(float);  // 37376 B
    cudaFuncSetAttribute(ceq_kernel, cudaFuncAttributeMaxDynamicSharedMemorySize, smem);

    ceq_kernel<<<NMOL, NA, smem>>>(eneg, pos, attrs, hard, Qtot, Zs, out);
}

// round 12
// speedup vs baseline: 1.0788x; 1.0788x over previous
#include <cuda_runtime.h>
#include <math.h>

// ChargeEquilibrationBlock: B=1024 molecules x n=128 atoms.
// Packed-triangle blocked Cholesky (NB=32), lookahead, fused forward solve,
// register-resident panel, conflict-free vector smem paths (R9 structure).
// R12: two-phase overlap slots — urgent units (next panel's diag-block
// columns) split across ALL warps, then a barrier, then panel || lazy
// trailing. Fixes R11's race (panel reading pre-update entries) while
// still relieving the owner warp. 6 CTAs/SM.

#define NMOL 1024
#define NA   128
#define NB   32
#define NE   10
#define FULL 0xffffffffu
#define TRI_WORDS 8448   // rowp(128)

typedef unsigned long long ull;

// packed row offset: rows padded to multiple of 4 words (16B aligned)
__device__ __forceinline__ int rowp(int i) {
    const int q = i >> 2, r = i & 3;
    return ((q * (q - 1)) << 3) + ((r * q) << 2) + (i << 2);
}

__device__ __forceinline__ ull fma2(ull a, ull b, ull c) {
    ull d;
    asm("fma.rn.f32x2 %0, %1, %2, %3;" : "=l"(d) : "l"(a), "l"(b), "l"(c));
    return d;
}
__device__ __forceinline__ float hsum2(ull a) {
    return __uint_as_float((unsigned)a) + __uint_as_float((unsigned)(a >> 32));
}

// build entries (i, j) for j in [jlo, jhi) with j < i; 4 erf chains in
// flight, STS.128 fast path when the whole quad is valid.
__device__ __forceinline__ void build_range(float* A, const float4* pq,
                                            int i, int jlo, int jhi) {
    const float4 pi = pq[i];
    float* Ri = A + rowp(i);
    const float is2 = 0.70710678118654752f;
    for (int g = (jlo & ~3); g < jhi; g += 4) {
        float v[4];
        #pragma unroll
        for (int k = 0; k < 4; k++) {
            int j = min(g + k, NA - 1);             // clamp: no OOB pq read
            float4 p = pq[j];                       // broadcast (lockstep)
            float dx = pi.x - p.x, dy = pi.y - p.y, dz = pi.z - p.z;
            float sq = dx * dx + dy * dy + dz * dz;
            float rd = rsqrtf(sq);                  // 1/d
            float gi = rsqrtf(pi.w + p.w);          // 1/gamma
            v[k] = erff(sq * rd * is2 * gi) * rd;   // erf(d/(sqrt2 gamma))/d
        }
        if (g >= jlo && g + 4 <= jhi && g + 3 < i) {
            *(float4*)&Ri[g] = make_float4(v[0], v[1], v[2], v[3]);
        } else {
            #pragma unroll
            for (int k = 0; k < 4; k++) {
                int j = g + k;
                if (j >= jlo && j < jhi && j < i) Ri[j] = v[k];
            }
        }
    }
}

// trailing units: row ti, j-groups [g0, g1) of block at column base s.
__device__ __forceinline__ void trail_units(float* A, int ti, int s,
                                            int g0, int g1) {
    float* Ti = A + rowp(ti);
    ull la[16];
    const ulonglong2* Lp = (const ulonglong2*)(Ti + s);
    #pragma unroll
    for (int q = 0; q < 8; q++) { ulonglong2 t = Lp[q]; la[2*q] = t.x; la[2*q+1] = t.y; }
    int j    = s + NB + 4 * g0;
    int joff = rowp(j);
    for (int jg = g0; jg < g1; jg++, j += 4) {
        const int len = j + 4;
        const ulonglong2* R0 = (const ulonglong2*)(A + joff           + s);
        const ulonglong2* R1 = (const ulonglong2*)(A + joff +   len   + s);
        const ulonglong2* R2 = (const ulonglong2*)(A + joff + 2*len   + s);
        const ulonglong2* R3 = (const ulonglong2*)(A + joff + 3*len   + s);
        ull a0 = 0ull, a1 = 0ull, a2 = 0ull, a3 = 0ull;
        #pragma unroll
        for (int q = 0; q < 8; q++) {               // broadcast LDS.128, lockstep j
            ulonglong2 c0 = R0[q], c1 = R1[q], c2 = R2[q], c3 = R3[q];
            a0 = fma2(la[2*q], c0.x, a0); a0 = fma2(la[2*q+1], c0.y, a0);
            a1 = fma2(la[2*q], c1.x, a1); a1 = fma2(la[2*q+1], c1.y, a1);
            a2 = fma2(la[2*q], c2.x, a2); a2 = fma2(la[2*q+1], c2.y, a2);
            a3 = fma2(la[2*q], c3.x, a3); a3 = fma2(la[2*q+1], c3.y, a3);
        }
        if (j <= ti) {                              // partial group -> padding
            float4 av = *(float4*)&Ti[j];
            av.x -= hsum2(a0); av.y -= hsum2(a1);
            av.z -= hsum2(a2); av.w -= hsum2(a3);
            *(float4*)&Ti[j] = av;
        }
        joff += 4 * len;
    }
}

// REGISTER-RESIDENT panel factorization + fused diag forward solve.
__device__ __noinline__ void panel_and_y(float* A, float* rinvS,
                                         float* xs1, float* xs2,
                                         int kb, int lane,
                                         float& v1, float& v2) {
    float* Arow = A + rowp(kb + lane);
    const int qmax = lane >> 2;                     // valid quads 0..qmax
    float r[NB];
    #pragma unroll
    for (int q = 0; q < 8; q++)
        if (q <= qmax) {
            float4 t = *(const float4*)&Arow[kb + 4 * q];
            r[4*q] = t.x; r[4*q+1] = t.y; r[4*q+2] = t.z; r[4*q+3] = t.w;
        }
    float rvown = 0.0f;
    #pragma unroll
    for (int m = 0; m < NB; m++) {
        const float dg = __shfl_sync(FULL, r[m], m);   // updated diag of row m
        const float rv = rsqrtf(dg);
        float lv;
        if (lane == m) { lv = dg * rv; rinvS[kb + m] = rv; rvown = rv; }
        else            lv = r[m] * rv;
        if (lane >= m) r[m] = lv;                   // L value (diag or below)
        lv = (lane > m) ? lv : 0.0f;                // update uses strict-below
        #pragma unroll
        for (int j = m + 1; j < NB; j++) {
            float ljm = __shfl_sync(FULL, lv, j);   // sources j > m: valid
            if (j <= lane) r[j] -= lv * ljm;
        }
    }
    // fused forward diag solve: L_bb y = b (L row in registers)
    #pragma unroll
    for (int m = 0; m < NB; m++) {
        float x1 = __shfl_sync(FULL, v1 * rvown, m);
        float x2 = __shfl_sync(FULL, v2 * rvown, m);
        if (lane > m) { v1 -= r[m] * x1; v2 -= r[m] * x2; }
    }
    v1 *= rvown; v2 *= rvown;                       // y for this row
    xs1[kb + lane] = v1; xs2[kb + lane] = v2;
    #pragma unroll
    for (int q = 0; q < 8; q++)                     // store L rows back
        if (q <= qmax)
            *(float4*)&Arow[kb + 4 * q] =
                make_float4(r[4*q], r[4*q+1], r[4*q+2], r[4*q+3]);
}

__global__ __launch_bounds__(NA, 6)
void ceq_kernel(const float* __restrict__ eneg,
                const float* __restrict__ pos,
                const float* __restrict__ attrs,
                const float* __restrict__ hard,
                const float* __restrict__ Qtot,
                const int*   __restrict__ Zs,
                float* __restrict__ out)
{
    extern __shared__ float s[];
    float*  A     = s;                    // packed lower triangle
    float*  rinvS = A + TRI_WORDS;        // 128: 1/L_ii
    float*  xs1   = rinvS + NA;           // solve broadcast, RHS 1
    float*  xs2   = xs1 + NA;             // solve broadcast, RHS 2
    float4* pq    = (float4*)(xs2 + NA);  // 128: (x, y, z, sigma)
    __shared__ float r1s[4], r2s[4];

    const int mol  = blockIdx.x;
    const int tid  = threadIdx.x;
    const int lane = tid & 31;
    const int wid  = tid >> 5;
    const int gid  = mol * NA + tid;
    float* Arow = A + rowp(tid);

    // ---- per-atom setup ----
    const float x = pos[gid * 3 + 0];
    const float y = pos[gid * 3 + 1];
    const float z = pos[gid * 3 + 2];
    const int Z = Zs[gid];
    const float r  = 0.3f + 0.02f * (float)Z;       // COV_RADII[Z]
    const float sg = r * r;
    pq[tid] = make_float4(x, y, z, sg);

    const float* arow = attrs + gid * NE;           // first-max argmax
    int am = 0; float mv = arow[0];
    #pragma unroll
    for (int e = 1; e < NE; e++) { float v = arow[e]; if (v > mv) { mv = v; am = e; } }

    const float diag = hard[am] + 1.0f / (1.7724538509055159f * r);  // sqrt(pi)
    float v1 = -eneg[gid];                          // RHS 1: -chi
    float v2 = 1.0f;                                // RHS 2: ones
    __syncthreads();                                // pq visible

    Arow[tid] = diag;                               // own diagonal

    // ---- build with panel-0 overlap ----
    if (wid == 0) {
        build_range(A, pq, lane, 0, 31);            // rows 0..31 (panel block)
        __syncwarp();
        panel_and_y(A, rinvS, xs1, xs2, 0, lane, v1, v2);
    } else if (wid == 1) {
        build_range(A, pq, 32 + lane, 0, 63);
        build_range(A, pq, 96 + lane, 0, 32);
    } else if (wid == 2) {
        build_range(A, pq, 64 + lane, 0, 95);
    } else {
        build_range(A, pq, 96 + lane, 32, 127);
    }
    __syncthreads();                                // BAR_A(0): build + panel0 + y0

    // ---- lookahead factorization ----
    for (int b = 0; b < 3; b++) {
        const int sb = 32 * b;

        // TRSM_b: rows below panel -> Lreg, float4 loads, fused fwd RHS
        if (tid >= sb + NB) {
            float Lreg[NB];
            int poff = rowp(sb);
            float4 aq;
            #pragma unroll
            for (int m = 0; m < NB; m++) {
                if ((m & 3) == 0)                   // quad-wise own-row load
                    aq = *(const float4*)&Arow[sb + m];
                const float am4 = ((m & 3) == 0) ? aq.x :
                                  ((m & 3) == 1) ? aq.y :
                                  ((m & 3) == 2) ? aq.z : aq.w;
                const float* Pm = A + poff + sb;    // panel row m (broadcast)
                float ve = 0.0f, vo = 0.0f;
                #pragma unroll
                for (int q = 0; q < NB / 4; q++) {
                    if (4 * q + 4 <= m) {           // full quads (compile-time)
                        float4 c = *(const float4*)(Pm + 4 * q);
                        ve += Lreg[4*q    ] * c.x + Lreg[4*q + 2] * c.z;
                        vo += Lreg[4*q + 1] * c.y + Lreg[4*q + 3] * c.w;
                    }
                }
                #pragma unroll
                for (int t = m & ~3; t < m; t++)    // remainder scalars
                    ve += Lreg[t] * Pm[t];
                Lreg[m] = (am4 - ve - vo) * rinvS[sb + m];
                poff += sb + (m & ~3) + 4;
            }
            #pragma unroll
            for (int m = 0; m < NB; m += 4)
                *(float4*)&Arow[sb + m] =
                    make_float4(Lreg[m], Lreg[m+1], Lreg[m+2], Lreg[m+3]);
            #pragma unroll
            for (int q = 0; q < NB; q += 4) {       // fused forward RHS update
                float4 a1 = *(const float4*)&xs1[sb + q];
                float4 a2 = *(const float4*)&xs2[sb + q];
                v1 -= Lreg[q]*a1.x + Lreg[q+1]*a1.y + Lreg[q+2]*a1.z + Lreg[q+3]*a1.w;
                v2 -= Lreg[q]*a2.x + Lreg[q+1]*a2.y + Lreg[q+2]*a2.z + Lreg[q+3]*a2.w;
            }
        }
        __syncthreads();                            // BAR_B(b): L columns visible

        // two-phase overlap slot.
        // Phase 1: URGENT units (next panel's diag-block cols) split over
        // ALL warps; barrier; Phase 2: owner panel || lazy trailing.
        if (b == 0) {
            // urgent: rows 32-63, cols 32-63 = 8 units, 2 per warp
            trail_units(A, 32 + lane, 0, wid * 2, wid * 2 + 2);
            __syncthreads();                        // urgent visible to panel
            // lazy: rows 64-95 (16 units) + rows 96-127 (24 units) = 40
            if (wid == 1) {
                panel_and_y(A, rinvS, xs1, xs2, 32, lane, v1, v2);
            }
            else if (wid == 2) trail_units(A, 64 + lane, 0,  0, 14);
            else if (wid == 3) trail_units(A, 96 + lane, 0,  0, 13);
            else {             trail_units(A, 96 + lane, 0, 13, 24);
                               trail_units(A, 64 + lane, 0, 14, 16); }
        } else if (b == 1) {
            // urgent: rows 64-95, cols 64-95 = 8 units, 2 per warp
            trail_units(A, 64 + lane, 32, wid * 2, wid * 2 + 2);
            __syncthreads();                        // urgent visible to panel
            // lazy: rows 96-127 = 16 units
            if (wid == 2) {
                panel_and_y(A, rinvS, xs1, xs2, 64, lane, v1, v2);
            }
            else if (wid == 3) trail_units(A, 96 + lane, 32,  0,  6);
            else if (wid == 1) trail_units(A, 96 + lane, 32,  6, 11);
            else               trail_units(A, 96 + lane, 32, 11, 16);
        } else {  // b == 2: 8 units split across ALL warps, then panel 3
            trail_units(A, 96 + lane, 64, wid * 2, wid * 2 + 2);
            __syncthreads();
            if (wid == 3)
                panel_and_y(A, rinvS, xs1, xs2, 96, lane, v1, v2);
        }
        __syncthreads();                            // BAR_A(b+1)
    }
    // factorization + forward solve complete: v = y

    // ---- backward solve L^T x = y (2 RHS), blocked ----
    for (int b = 3; b >= 0; b--) {
        const int kb = b * NB;
        if (wid == b) {
            float lcol[NB];
            int coff = rowp(kb);
            #pragma unroll
            for (int m = 0; m < NB; m++) {
                lcol[m] = A[coff + tid];            // consecutive lanes: no conflict
                coff += kb + (m & ~3) + 4;
            }
            const float rv = rinvS[tid];
            #pragma unroll
            for (int m = NB - 1; m >= 0; m--) {
                float x1 = __shfl_sync(FULL, v1 * rv, m);
                float x2 = __shfl_sync(FULL, v2 * rv, m);
                if (lane < m) { v1 -= lcol[m] * x1; v2 -= lcol[m] * x2; }
            }
            v1 *= rv; v2 *= rv;
            xs1[tid] = v1; xs2[tid] = v2;
        }
        __syncthreads();
        if (tid < kb) {
            int coff = rowp(kb);
            #pragma unroll
            for (int m = 0; m < NB; m++) {
                float l = A[coff + tid];
                v1 -= l * xs1[kb + m];
                v2 -= l * xs2[kb + m];
                coff += kb + (m & ~3) + 4;
            }
        }
    }

    // v1 = A^{-1}(-chi), v2 = A^{-1} 1
    float s1 = v1, s2 = v2;
    #pragma unroll
    for (int o = 16; o > 0; o >>= 1) {
        s1 += __shfl_xor_sync(FULL, s1, o);
        s2 += __shfl_xor_sync(FULL, s2, o);
    }
    if (lane == 0) { r1s[wid] = s1; r2s[wid] = s2; }
    __syncthreads();
    s1 = r1s[0] + r1s[1] + r1s[2] + r1s[3];
    s2 = r2s[0] + r2s[1] + r2s[2] + r2s[3];

    const float lam = (s1 - Qtot[mol]) / (s2 - 1.0f);
    out[gid] = v1 - lam * v2;
}

extern "C" void kernel_launch(void* const* d_in, const int* in_sizes, int n_in,
                              void* d_out, int out_size)
{
    const float* eneg  = (const float*)d_in[0];
    const float* pos   = (const float*)d_in[1];
    const float* attrs = (const float*)d_in[2];
    const float* hard  = (const float*)d_in[3];
    const float* Qtot  = (const float*)d_in[4];
    const int*   Zs    = (const int*)d_in[6];
    float* out = (float*)d_out;

    const int smem = (TRI_WORDS + 3 * NA + NA * 4) * (int)sizeof(float);  // 37376 B
    cudaFuncSetAttribute(ceq_kernel, cudaFuncAttributeMaxDynamicSharedMemorySize, smem);

    ceq_kernel<<<NMOL, NA, smem>>>(eneg, pos, attrs, hard, Qtot, Zs, out);
}